// round 17
// baseline (speedup 1.0000x reference)
#include <cuda_runtime.h>
#include <cuda_bf16.h>
#include <cuda_fp16.h>
#include <cstdint>

#define N_NODES 40000
#define N_EDGES 640000
#define D 128
#define NB 157  // ceil(40000/256) scan blocks

// ---------------- scratch (device globals, referenced by symbol only) ----------------
__device__ __half g_h[N_NODES * D];     // GEMM output (per layer), fp16
__device__ __half g_xh[N_NODES * D];    // fp16 x
__device__ __half g_yh[N_NODES * D];    // fp16 layer-1 output
__device__ __half g_w1h[D * D], g_w2h[D * D];
__device__ int   g_deg[N_NODES];
__device__ int   g_rowptr[N_NODES + 1];
__device__ int   g_cursor[N_NODES];
__device__ int   g_srcs[N_EDGES];
__device__ float g_scale[N_EDGES];
__device__ int   g_is32;
__device__ int   g_bsum[NB];
__device__ int   g_boff[NB];

__device__ __forceinline__ int load_idx(const void* ei, int pos) {
    if (g_is32) return ((const int*)ei)[pos];
    return (int)((const long long*)ei)[pos];
}

// ---------------- prep_init: zero deg + dtype detect (tiny; runs before fork) ----------------
__global__ __launch_bounds__(256) void prep_init_kernel(const int* __restrict__ ei32) {
    int i = blockIdx.x * 256 + threadIdx.x;
    if (i < N_NODES) g_deg[i] = 0;
    if (blockIdx.x == 0) {
        int nz = 0;
        for (int s = threadIdx.x; s < 4096; s += 256)
            nz |= (ei32[2 * s + 1] != 0);
        nz = __syncthreads_or(nz);
        if (threadIdx.x == 0) g_is32 = nz;
    }
}

// ---------------- prep_conv: x->fp16, W->fp16 (main-stream branch) ----------------
#define PREP_X_BLOCKS 5000
#define PREP_W_BLOCKS 32
#define PREP_CONV_GRID (PREP_X_BLOCKS + PREP_W_BLOCKS)
__global__ __launch_bounds__(256) void prep_conv_kernel(const float* __restrict__ x,
                                                        const float* __restrict__ W1,
                                                        const float* __restrict__ W2) {
    int b = blockIdx.x;
    if (b < PREP_X_BLOCKS) {
        int i = b * 256 + threadIdx.x;            // float4 index; 1.28M total
        if (i * 4 < N_NODES * D) {
            float4 v = reinterpret_cast<const float4*>(x)[i];
            __half2 h0 = __floats2half2_rn(v.x, v.y);
            __half2 h1 = __floats2half2_rn(v.z, v.w);
            reinterpret_cast<__half2*>(g_xh)[2 * i]     = h0;
            reinterpret_cast<__half2*>(g_xh)[2 * i + 1] = h1;
        }
        return;
    }
    b -= PREP_X_BLOCKS;
    {
        int i = b * 256 + threadIdx.x;            // 0..8191
        const float* src = (i < 4096) ? W1 : W2;
        __half* dh = (i < 4096) ? g_w1h : g_w2h;
        int j = i & 4095;
        float4 v = reinterpret_cast<const float4*>(src)[j];
        __half2 h0 = __floats2half2_rn(v.x, v.y);
        __half2 h1 = __floats2half2_rn(v.z, v.w);
        reinterpret_cast<__half2*>(dh)[2 * j]     = h0;
        reinterpret_cast<__half2*>(dh)[2 * j + 1] = h1;
    }
}

// ---------------- CSR build (side-stream branch) ----------------
__global__ void count_kernel(const void* __restrict__ ei) {
    int e = blockIdx.x * blockDim.x + threadIdx.x;
    if (e >= N_EDGES) return;
    int dst = load_idx(ei, N_EDGES + e);
    if ((unsigned)dst < (unsigned)N_NODES) atomicAdd(&g_deg[dst], 1);
}

__global__ __launch_bounds__(256) void bsum_kernel() {
    int i = blockIdx.x * 256 + threadIdx.x;
    int v = (i < N_NODES) ? g_deg[i] : 0;
#pragma unroll
    for (int off = 16; off > 0; off >>= 1)
        v += __shfl_down_sync(0xffffffffu, v, off);
    __shared__ int ws[8];
    int wid = threadIdx.x >> 5, lane = threadIdx.x & 31;
    if (lane == 0) ws[wid] = v;
    __syncthreads();
    if (threadIdx.x == 0) {
        int s = 0;
#pragma unroll
        for (int w = 0; w < 8; w++) s += ws[w];
        g_bsum[blockIdx.x] = s;
    }
}

__global__ __launch_bounds__(256) void bscan_kernel() {
    int t = threadIdx.x;
    int lane = t & 31, wid = t >> 5;
    int v = (t < NB) ? g_bsum[t] : 0;
    int orig = v;
#pragma unroll
    for (int off = 1; off < 32; off <<= 1) {
        int u = __shfl_up_sync(0xffffffffu, v, off);
        if (lane >= off) v += u;
    }
    __shared__ int wsum[8];
    if (lane == 31) wsum[wid] = v;
    __syncthreads();
    if (wid == 0) {
        int s = (lane < 8) ? wsum[lane] : 0;
#pragma unroll
        for (int off = 1; off < 8; off <<= 1) {
            int u = __shfl_up_sync(0xffffffffu, s, off);
            if (lane >= off) s += u;
        }
        if (lane < 8) wsum[lane] = s;
    }
    __syncthreads();
    int incl = v + (wid > 0 ? wsum[wid - 1] : 0);
    if (t < NB) g_boff[t] = incl - orig;
}

__global__ __launch_bounds__(256) void rowptr_kernel() {
    int i = blockIdx.x * 256 + threadIdx.x;
    int lane = threadIdx.x & 31, wid = threadIdx.x >> 5;
    int v = (i < N_NODES) ? g_deg[i] : 0;
    int orig = v;
#pragma unroll
    for (int off = 1; off < 32; off <<= 1) {
        int u = __shfl_up_sync(0xffffffffu, v, off);
        if (lane >= off) v += u;
    }
    __shared__ int wsum[8];
    if (lane == 31) wsum[wid] = v;
    __syncthreads();
    if (wid == 0) {
        int s = (lane < 8) ? wsum[lane] : 0;
#pragma unroll
        for (int off = 1; off < 8; off <<= 1) {
            int u = __shfl_up_sync(0xffffffffu, s, off);
            if (lane >= off) s += u;
        }
        if (lane < 8) wsum[lane] = s;
    }
    __syncthreads();
    int incl = v + (wid > 0 ? wsum[wid - 1] : 0);
    int excl = incl - orig + g_boff[blockIdx.x];
    if (i < N_NODES) {
        g_rowptr[i] = excl;
        g_cursor[i] = excl;
        if (i == N_NODES - 1) g_rowptr[N_NODES] = excl + orig;
    }
}

__global__ void fill_kernel(const void* __restrict__ ei,
                            const float* __restrict__ ea) {
    int e = blockIdx.x * blockDim.x + threadIdx.x;
    if (e >= N_EDGES) return;
    int src = load_idx(ei, e);
    int dst = load_idx(ei, N_EDGES + e);
    if ((unsigned)dst >= (unsigned)N_NODES) return;
    if ((unsigned)src >= (unsigned)N_NODES) return;
    int pos = atomicAdd(&g_cursor[dst], 1);
    g_srcs[pos]  = src;
    g_scale[pos] = 1.0f / ea[e];
}

// ---------------- fp16 tensor-core GEMM via mma.sync: g_h = X @ W^T ----------------
// CTA: 128x128 tile (grid 313, single wave at 3 CTAs/SM), 8 warps (4m x 2n),
// warp tile 32x64. Single-term fp16 mma, fp32 accumulate.
// OOB A rows handled via cp.async zero-fill (src-size = 0).
#define SP 136                          // padded row stride (fp16 elems)
#define T_TILE_B (128 * SP * 2)         // 34816 bytes per tile
#define OFF_A 0
#define OFF_B (T_TILE_B)
#define GEMM_SMEM (2 * T_TILE_B)        // 69632

__device__ __forceinline__ void ldsm4(uint32_t* r, uint32_t addr) {
    asm volatile("ldmatrix.sync.aligned.m8n8.x4.shared.b16 {%0,%1,%2,%3}, [%4];"
                 : "=r"(r[0]), "=r"(r[1]), "=r"(r[2]), "=r"(r[3]) : "r"(addr));
}
__device__ __forceinline__ void mma16816h(float* d, const uint32_t* a, uint32_t b0, uint32_t b1) {
    asm volatile(
        "mma.sync.aligned.m16n8k16.row.col.f32.f16.f16.f32 "
        "{%0,%1,%2,%3}, {%4,%5,%6,%7}, {%8,%9}, {%0,%1,%2,%3};"
        : "+f"(d[0]), "+f"(d[1]), "+f"(d[2]), "+f"(d[3])
        : "r"(a[0]), "r"(a[1]), "r"(a[2]), "r"(a[3]), "r"(b0), "r"(b1));
}
__device__ __forceinline__ void cp16(uint32_t saddr, const void* gptr) {
    asm volatile("cp.async.cg.shared.global [%0], [%1], 16;" :: "r"(saddr), "l"(gptr));
}
__device__ __forceinline__ void cp16z(uint32_t saddr, const void* gptr, bool valid) {
    int sz = valid ? 16 : 0;
    asm volatile("cp.async.cg.shared.global [%0], [%1], 16, %2;"
                 :: "r"(saddr), "l"(gptr), "r"(sz));
}

__global__ __launch_bounds__(256, 3) void gemm_mma_kernel(int layer) {
    extern __shared__ char smem[];
    uint32_t sb;
    asm("{ .reg .u64 t; cvta.to.shared.u64 t, %1; cvt.u32.u64 %0, t; }" : "=r"(sb) : "l"(smem));
    const int tid  = threadIdx.x;
    const int wid  = tid >> 5;
    const int lane = tid & 31;
    const int lane8 = lane & 7;
    const int g     = lane >> 3;
    const int m0 = (wid & 3) * 32;       // 4 m-groups of 32 rows
    const int n0 = (wid >> 2) * 64;      // 2 n-groups of 64 cols
    const int block_row = blockIdx.x * 128;

    const __half* A = (layer == 0) ? g_xh : g_yh;
    const __half* B = (layer == 0) ? g_w1h : g_w2h;

    // ---- issue all tile loads via cp.async ----
    // A tile: 128 rows x 128 cols fp16 = 2048 uint4; 8 per thread (zero-fill OOB rows)
#pragma unroll
    for (int it = 0; it < 8; it++) {
        int idx = tid + it * 256;
        int r = idx >> 4;                // 0..127
        int c = (idx & 15) * 8;          // 0..120
        int gr = block_row + r;
        uint32_t so = (uint32_t)(r * SP + c) * 2;
        cp16z(sb + OFF_A + so, A + (size_t)gr * D + c, gr < N_NODES);
    }
    // B tile: 128 rows x 128 cols fp16 = 2048 uint4; 8 per thread
#pragma unroll
    for (int it = 0; it < 8; it++) {
        int idx = tid + it * 256;
        int r = idx >> 4;                // 0..127
        int c = (idx & 15) * 8;
        uint32_t so = (uint32_t)(r * SP + c) * 2;
        cp16(sb + OFF_B + so, B + (size_t)r * D + c);
    }
    asm volatile("cp.async.commit_group;" ::: "memory");

    float acc[2][8][4];
#pragma unroll
    for (int i = 0; i < 2; i++)
#pragma unroll
        for (int j = 0; j < 8; j++)
#pragma unroll
            for (int c = 0; c < 4; c++) acc[i][j][c] = 0.0f;

    asm volatile("cp.async.wait_group 0;" ::: "memory");
    __syncthreads();

#pragma unroll
    for (int k16 = 0; k16 < 8; k16++) {
        const int k0 = k16 * 16;
        uint32_t a[2][4];
#pragma unroll
        for (int mi = 0; mi < 2; mi++) {
            int arow = m0 + mi * 16 + ((g & 1) << 3) + lane8;
            int acol = k0 + ((g >> 1) << 3);
            uint32_t ao = (uint32_t)(arow * SP + acol) * 2;
            ldsm4(a[mi], sb + OFF_A + ao);
        }
#pragma unroll
        for (int jj = 0; jj < 4; jj++) {
            int brow = n0 + jj * 16 + ((g >> 1) << 3) + lane8;
            int bcol = k0 + ((g & 1) << 3);
            uint32_t bo = (uint32_t)(brow * SP + bcol) * 2;
            uint32_t bh[4];
            ldsm4(bh, sb + OFF_B + bo);
#pragma unroll
            for (int f = 0; f < 2; f++) {
                uint32_t b0 = bh[2 * f], b1 = bh[2 * f + 1];
#pragma unroll
                for (int mi = 0; mi < 2; mi++)
                    mma16816h(acc[mi][jj * 2 + f], a[mi], b0, b1);
            }
        }
    }

    // epilogue: write fp16 to g_h (guard rows: 313*128 = 40064 > 40000)
#pragma unroll
    for (int mi = 0; mi < 2; mi++) {
#pragma unroll
        for (int j = 0; j < 8; j++) {
            int row = block_row + m0 + mi * 16 + (lane >> 2);
            int col = n0 + j * 8 + (lane & 3) * 2;
            float* d = acc[mi][j];
            if (row < N_NODES)
                *reinterpret_cast<__half2*>((__half*)g_h + (size_t)row * D + col) =
                    __floats2half2_rn(d[0], d[1]);
            if (row + 8 < N_NODES)
                *reinterpret_cast<__half2*>((__half*)g_h + (size_t)(row + 8) * D + col) =
                    __floats2half2_rn(d[2], d[3]);
        }
    }
}

// ---------------- aggregate: relu( sum_{e in CSR[n]} g_h[src_e]*scale_e + bias ) ----------------
// layer 0 -> writes fp16 g_yh; layer 1 -> writes fp32 out_ext.
__global__ __launch_bounds__(256) void agg_kernel(const float* __restrict__ bias,
                                                  float* __restrict__ out_ext,
                                                  int layer) {
    int warp = (blockIdx.x * blockDim.x + threadIdx.x) >> 5;
    int lane = threadIdx.x & 31;
    if (warp >= N_NODES) return;
    const __half* H = (const __half*)g_h;
    int begin = g_rowptr[warp];
    int end   = g_rowptr[warp + 1];

    float4 acc = make_float4(0.f, 0.f, 0.f, 0.f);
    int i = begin;
    for (; i + 3 < end; i += 4) {
        int   s0 = g_srcs[i],   s1 = g_srcs[i+1], s2 = g_srcs[i+2], s3 = g_srcs[i+3];
        float w0 = g_scale[i],  w1 = g_scale[i+1], w2 = g_scale[i+2], w3 = g_scale[i+3];
        uint2 r0 = *reinterpret_cast<const uint2*>(H + (size_t)s0 * D + lane * 4);
        uint2 r1 = *reinterpret_cast<const uint2*>(H + (size_t)s1 * D + lane * 4);
        uint2 r2 = *reinterpret_cast<const uint2*>(H + (size_t)s2 * D + lane * 4);
        uint2 r3 = *reinterpret_cast<const uint2*>(H + (size_t)s3 * D + lane * 4);
        float2 a0 = __half22float2(*reinterpret_cast<__half2*>(&r0.x));
        float2 b0 = __half22float2(*reinterpret_cast<__half2*>(&r0.y));
        float2 a1 = __half22float2(*reinterpret_cast<__half2*>(&r1.x));
        float2 b1 = __half22float2(*reinterpret_cast<__half2*>(&r1.y));
        float2 a2 = __half22float2(*reinterpret_cast<__half2*>(&r2.x));
        float2 b2 = __half22float2(*reinterpret_cast<__half2*>(&r2.y));
        float2 a3 = __half22float2(*reinterpret_cast<__half2*>(&r3.x));
        float2 b3 = __half22float2(*reinterpret_cast<__half2*>(&r3.y));
        acc.x += w0 * a0.x; acc.y += w0 * a0.y; acc.z += w0 * b0.x; acc.w += w0 * b0.y;
        acc.x += w1 * a1.x; acc.y += w1 * a1.y; acc.z += w1 * b1.x; acc.w += w1 * b1.y;
        acc.x += w2 * a2.x; acc.y += w2 * a2.y; acc.z += w2 * b2.x; acc.w += w2 * b2.y;
        acc.x += w3 * a3.x; acc.y += w3 * a3.y; acc.z += w3 * b3.x; acc.w += w3 * b3.y;
    }
    for (; i < end; i++) {
        int   s0 = g_srcs[i];
        float w0 = g_scale[i];
        uint2 r0 = *reinterpret_cast<const uint2*>(H + (size_t)s0 * D + lane * 4);
        float2 a0 = __half22float2(*reinterpret_cast<__half2*>(&r0.x));
        float2 b0 = __half22float2(*reinterpret_cast<__half2*>(&r0.y));
        acc.x += w0 * a0.x; acc.y += w0 * a0.y; acc.z += w0 * b0.x; acc.w += w0 * b0.y;
    }

    float4 b = *reinterpret_cast<const float4*>(bias + lane * 4);
    float4 r;
    r.x = acc.x + b.x; r.x = r.x > 0.f ? r.x : 0.f;
    r.y = acc.y + b.y; r.y = r.y > 0.f ? r.y : 0.f;
    r.z = acc.z + b.z; r.z = r.z > 0.f ? r.z : 0.f;
    r.w = acc.w + b.w; r.w = r.w > 0.f ? r.w : 0.f;

    if (layer == 1) {
        *reinterpret_cast<float4*>(out_ext + (size_t)warp * D + lane * 4) = r;
    } else {
        size_t base = (size_t)warp * D + lane * 4;
        *reinterpret_cast<__half2*>((__half*)g_yh + base)     = __floats2half2_rn(r.x, r.y);
        *reinterpret_cast<__half2*>((__half*)g_yh + base + 2) = __floats2half2_rn(r.z, r.w);
    }
}

// ---------------- launch: two-branch graph (CSR build || conv+gemm1) ----------------
extern "C" void kernel_launch(void* const* d_in, const int* in_sizes, int n_in,
                              void* d_out, int out_size) {
    const float* x  = (const float*)d_in[0];
    const void*  ei = d_in[1];                 // int32 or int64, auto-detected
    const float* ea = (const float*)d_in[2];
    const float* W1 = (const float*)d_in[3];
    const float* b1 = (const float*)d_in[4];
    const float* W2 = (const float*)d_in[5];
    const float* b2 = (const float*)d_in[6];
    float* out = (float*)d_out;

    cudaFuncSetAttribute(gemm_mma_kernel, cudaFuncAttributeMaxDynamicSharedMemorySize, GEMM_SMEM);

    const int gemm_grid = (N_NODES + 127) / 128;        // 313 (single wave at 3/SM)
    const int agg_grid  = (N_NODES * 32 + 255) / 256;   // 5000 blocks
    const int edge_grid = (N_EDGES + 255) / 256;

    cudaStream_t s2;
    cudaEvent_t eFork, eJoin;
    cudaStreamCreateWithFlags(&s2, cudaStreamNonBlocking);
    cudaEventCreateWithFlags(&eFork, cudaEventDisableTiming);
    cudaEventCreateWithFlags(&eJoin, cudaEventDisableTiming);

    // prologue on main stream                                    // idx 0
    prep_init_kernel<<<NB, 256>>>((const int*)ei);

    // fork
    cudaEventRecord(eFork, 0);
    cudaStreamWaitEvent(s2, eFork, 0);

    // main branch conversions                                    // idx 1
    prep_conv_kernel<<<PREP_CONV_GRID, 256>>>(x, W1, W2);
    // side branch start                                          // idx 2
    count_kernel<<<edge_grid, 256, 0, s2>>>(ei);
    // main branch layer-1 GEMM                                   // idx 3 <- profiled
    gemm_mma_kernel<<<gemm_grid, 256, GEMM_SMEM>>>(0);
    // rest of side branch
    bsum_kernel<<<NB, 256, 0, s2>>>();
    bscan_kernel<<<1, 256, 0, s2>>>();
    rowptr_kernel<<<NB, 256, 0, s2>>>();
    fill_kernel<<<edge_grid, 256, 0, s2>>>(ei, ea);

    // join: agg1 needs both gemm1 (main) and fill (s2)
    cudaEventRecord(eJoin, s2);
    cudaStreamWaitEvent(0, eJoin, 0);

    agg_kernel<<<agg_grid, 256>>>(b1, out, 0);
    gemm_mma_kernel<<<gemm_grid, 256, GEMM_SMEM>>>(1);
    agg_kernel<<<agg_grid, 256>>>(b2, out, 1);

    cudaEventDestroy(eFork);
    cudaEventDestroy(eJoin);
    cudaStreamDestroy(s2);
}